// round 6
// baseline (speedup 1.0000x reference)
#include <cuda_runtime.h>
#include <math.h>

#define W_IMG 512
#define H_IMG 512
#define MAX_N (32 * W_IMG * H_IMG)
#define MAX_WORDS (MAX_N / 64)

// Per-node state, packed so label/area/runsum of a run-start share sectors.
struct Node { int label; int area; float runsum; };
__device__ Node g_node[MAX_N];
__device__ unsigned long long g_bits[MAX_WORDS];  // fg bitmask, 64 px/word
// acc: 0=f0 (Σ_fg bce/(w+1)), 2=Σ_roots a^1.5, 3=Σ_roots a, 4=Σ_all b, 5=Σ_fg b
__device__ double g_acc[6];

// ---------------------------------------------------------------------------
__device__ __forceinline__ int find_root(int x) {
    int p = g_node[x].label;
    while (p != x) { x = p; p = g_node[x].label; }
    return x;
}

__device__ __forceinline__ void merge(int a, int b) {
    bool done = false;
    do {
        a = find_root(a);
        b = find_root(b);
        if (a < b) { int t = a; a = b; b = t; }
        if (a != b) {
            int old = atomicMin(&g_node[a].label, b);
            done = (old == a);
            a = old;
        } else {
            done = true;
        }
    } while (!done);
}

__device__ __forceinline__ int rs_in_word(unsigned long long m, int k) {
    unsigned long long below = (k == 0) ? 0ull : ((1ull << k) - 1ull);
    unsigned long long z = (~m) & below;
    return z ? (64 - __clzll(z)) : 0;
}

__device__ __forceinline__ int run_len(unsigned long long m, int k) {
    unsigned long long inv = ~(m >> k);
    return inv ? (__ffsll((long long)inv) - 1) : (64 - k);
}

__device__ __forceinline__ double warp_sum(double v) {
#pragma unroll
    for (int off = 16; off > 0; off >>= 1)
        v += __shfl_down_sync(0xFFFFFFFFu, v, off);
    return v;
}

// ---------------------------------------------------------------------------
__global__ void k_zero() {
    if (threadIdx.x < 6) g_acc[threadIdx.x] = 0.0;
}

// ---------------------------------------------------------------------------
// k_main: fused prep + branchless bce. Thread per 16-px segment.
// Produces: g_bits, UF node init, per-run Σ(b-x) at run-start nodes,
// and global sums Σ_all b, Σ_fg b.
// ---------------------------------------------------------------------------
__global__ void k_main(const float* __restrict__ in,
                       const float* __restrict__ tgt, int nseg) {
    int t = blockIdx.x * blockDim.x + threadIdx.x;
    double dAll = 0.0, dFgb = 0.0;
    if (t < nseg) {
        int w = t >> 2, seg = t & 3, s0 = seg << 4;
        const float4* t4 = (const float4*)tgt;
        const float4* in4 = (const float4*)in;
        int gbase = w * 16 + seg * 4;

        // pass A: build 16-bit mask for my segment
        unsigned int m16 = 0;
#pragma unroll
        for (int g = 0; g < 4; g++) {
            float4 v = __ldg(&t4[gbase + g]);
            unsigned int nib = 0;
            if (v.x > 0.f) nib |= 1u;
            if (v.y > 0.f) nib |= 2u;
            if (v.z > 0.f) nib |= 4u;
            if (v.w > 0.f) nib |= 8u;
            m16 |= nib << (g * 4);
        }
        // assemble full 64-bit word across aligned 4-lane group
        unsigned long long m = ((unsigned long long)m16) << s0;
        m |= __shfl_xor_sync(0xFFFFFFFFu, m, 1);
        m |= __shfl_xor_sync(0xFFFFFFFFu, m, 2);
        if (seg == 0) g_bits[w] = m;

        bool carry_in = (seg > 0) && ((m >> (s0 - 1)) & 1ull);
        bool fg16 = (seg < 3) && ((m >> (s0 + 16)) & 1ull);
        int base = w << 6;

        // pass B: branchless bce + run-sum tracking
        float fAll = 0.f, fgb = 0.f;
        float head = 0.f;     // Σ(b-x) over leading fg-prefix of my segment
        bool pf = true;
        float run = 0.f;
        bool owned = false;
        int rs = 0;
        bool prev = carry_in;
        bool pend_f = false;
        int pend_node = 0;
        float pend_run = 0.f;

#pragma unroll
        for (int g = 0; g < 4; g++) {
            float4 v = __ldg(&in4[gbase + g]);
            float xs[4] = {v.x, v.y, v.z, v.w};
#pragma unroll
            for (int l = 0; l < 4; l++) {
                int k = g * 4 + l;
                float x = xs[l];
                float gpl = __logf(1.f + __expf(-fabsf(x)));
                float b = gpl + fmaxf(x, 0.f);   // bce if bg
                float c = b - x;                 // bce if fg
                bool fg = (m16 >> k) & 1u;
                fAll += b;
                fgb += fg ? b : 0.f;
                pf = pf && fg;
                head += pf ? c : 0.f;
                if (fg) {
                    if (!prev) {                 // run starts here (owned)
                        owned = true;
                        rs = k;
                        run = 0.f;
                        int node = base + s0 + k;
                        g_node[node].label = node;
                        g_node[node].area = 0;
                    }
                    run += c;
                    bool nxt = (k < 15) ? (((m16 >> (k + 1)) & 1u) != 0) : fg16;
                    if (owned) {
                        if (!nxt) {              // run ends within my view
                            g_node[base + s0 + rs].runsum = run;
                            owned = false;
                        } else if (k == 15) {    // continues into next segment
                            pend_f = true;
                            pend_node = base + s0 + rs;
                            pend_run = run;
                        }
                    }
                }
                prev = fg;
            }
        }

        // resolve cross-segment continuation via shfl (run never crosses word)
        bool full = (m16 == 0xFFFFu) && (seg < 3);
        float h1 = __shfl_down_sync(0xFFFFFFFFu, head, 1);
        float h2 = __shfl_down_sync(0xFFFFFFFFu, head, 2);
        float h3 = __shfl_down_sync(0xFFFFFFFFu, head, 3);
        unsigned int f1 = __shfl_down_sync(0xFFFFFFFFu, (unsigned int)full, 1);
        unsigned int f2 = __shfl_down_sync(0xFFFFFFFFu, (unsigned int)full, 2);
        float ext = h1 + (f1 ? (h2 + (f2 ? h3 : 0.f)) : 0.f);
        if (pend_f) g_node[pend_node].runsum = pend_run + ext;

        dAll = fAll;
        dFgb = fgb;
    }

    // block reduce -> g_acc[4], g_acc[5]
    __shared__ double sh[2][8];
    int lane = threadIdx.x & 31;
    int warp = threadIdx.x >> 5;
    dAll = warp_sum(dAll);
    dFgb = warp_sum(dFgb);
    if (lane == 0) { sh[0][warp] = dAll; sh[1][warp] = dFgb; }
    __syncthreads();
    if (warp == 0) {
        int nw = blockDim.x >> 5;
        double v0 = (lane < nw) ? sh[0][lane] : 0.0;
        double v1 = (lane < nw) ? sh[1][lane] : 0.0;
        v0 = warp_sum(v0);
        v1 = warp_sum(v1);
        if (lane == 0) {
            atomicAdd(&g_acc[4], v0);
            atomicAdd(&g_acc[5], v1);
        }
    }
}

// ---------------------------------------------------------------------------
// k_union: word-level bitmask merges
// ---------------------------------------------------------------------------
__global__ void k_union(int nwords) {
    int w = blockIdx.x * blockDim.x + threadIdx.x;
    if (w >= nwords) return;
    unsigned long long cur = g_bits[w];
    if (!cur) return;
    int base = w << 6;
    int wx = w & 7;
    int wy = (w >> 3) & (H_IMG - 1);

    if (wx && (cur & 1ull)) {
        unsigned long long L = g_bits[w - 1];
        if (L >> 63) merge(base, ((w - 1) << 6) + rs_in_word(L, 63));
    }
    if (wy) {
        unsigned long long up = g_bits[w - 8];
        unsigned long long ov = cur & up;
        unsigned long long need = ov & ~(ov << 1);
        while (need) {
            int k = __ffsll((long long)need) - 1;
            need &= need - 1;
            merge(base + rs_in_word(cur, k),
                  ((w - 8) << 6) + rs_in_word(up, k));
        }
    }
}

// ---------------------------------------------------------------------------
// k_area: per owned run-start -> compress to final root + area accumulate
// ---------------------------------------------------------------------------
__global__ void k_area(int nseg) {
    int t = blockIdx.x * blockDim.x + threadIdx.x;
    if (t >= nseg) return;
    int w = t >> 2, seg = t & 3, s0 = seg << 4;
    unsigned long long cur = g_bits[w];
    unsigned int m16 = (unsigned int)((cur >> s0) & 0xFFFFull);
    if (!m16) return;
    bool carry_in = (seg > 0) && ((cur >> (s0 - 1)) & 1ull);
    unsigned int starts = m16 & ~((m16 << 1) | (carry_in ? 1u : 0u));
    starts &= 0xFFFFu;
    int base = w << 6;
    while (starts) {
        int k = __ffs(starts) - 1;
        starts &= starts - 1;
        int kk = s0 + k;
        int node = base + kk;
        int root = find_root(node);
        if (root != node) g_node[node].label = root;
        atomicAdd(&g_node[root].area, run_len(cur, kk));
    }
}

// ---------------------------------------------------------------------------
// k_runs: per owned run-start -> f0 += runsum/(sqrt(area)+1);
// per root -> Σ a^1.5 and Σ a.
// ---------------------------------------------------------------------------
__global__ void k_runs(int nseg) {
    double d0 = 0.0, d2 = 0.0, d3 = 0.0;
    int t = blockIdx.x * blockDim.x + threadIdx.x;
    if (t < nseg) {
        int w = t >> 2, seg = t & 3, s0 = seg << 4;
        unsigned long long cur = g_bits[w];
        unsigned int m16 = (unsigned int)((cur >> s0) & 0xFFFFull);
        if (m16) {
            bool carry_in = (seg > 0) && ((cur >> (s0 - 1)) & 1ull);
            unsigned int starts = m16 & ~((m16 << 1) | (carry_in ? 1u : 0u));
            starts &= 0xFFFFu;
            int base = w << 6;
            float f0 = 0.f, fs2 = 0.f, fs3 = 0.f;
            while (starts) {
                int k = __ffs(starts) - 1;
                starts &= starts - 1;
                int node = base + s0 + k;
                int root = g_node[node].label;       // compressed
                float rsum = g_node[node].runsum;
                if (root == node) {
                    float fa = (float)g_node[node].area;
                    float sq = sqrtf(fa);
                    fs2 += fa * sq;
                    fs3 += fa;
                    f0 += rsum * __fdividef(1.f, sq + 1.f);
                } else {
                    float fa = (float)__ldg(&g_node[root].area);
                    f0 += rsum * __fdividef(1.f, sqrtf(fa) + 1.f);
                }
            }
            d0 = f0; d2 = fs2; d3 = fs3;
        }
    }

    __shared__ double sh[3][8];
    int lane = threadIdx.x & 31;
    int warp = threadIdx.x >> 5;
    d0 = warp_sum(d0); d2 = warp_sum(d2); d3 = warp_sum(d3);
    if (lane == 0) { sh[0][warp] = d0; sh[1][warp] = d2; sh[2][warp] = d3; }
    __syncthreads();
    if (warp == 0) {
        int nw = blockDim.x >> 5;
        double v0 = (lane < nw) ? sh[0][lane] : 0.0;
        double v2 = (lane < nw) ? sh[1][lane] : 0.0;
        double v3 = (lane < nw) ? sh[2][lane] : 0.0;
        v0 = warp_sum(v0); v2 = warp_sum(v2); v3 = warp_sum(v3);
        if (lane == 0) {
            atomicAdd(&g_acc[0], v0);
            atomicAdd(&g_acc[2], v2);
            atomicAdd(&g_acc[3], v3);
        }
    }
}

__global__ void k_final(float* __restrict__ out, double inv_n) {
    double s3 = g_acc[3];
    double mean_nz = g_acc[2] / (s3 > 0.0 ? s3 : 1.0);
    double f1 = g_acc[4] - g_acc[5];   // Σ_bg bce = Σ_all b - Σ_fg b
    double loss = (g_acc[0] + f1 / (mean_nz + 1.0)) * inv_n;
    out[0] = (float)loss;
}

// ---------------------------------------------------------------------------
extern "C" void kernel_launch(void* const* d_in, const int* in_sizes, int n_in,
                              void* d_out, int out_size) {
    const float* inputs  = (const float*)d_in[0];
    const float* targets = (const float*)d_in[1];
    float* out = (float*)d_out;

    int n = in_sizes[0];
    int nwords = n >> 6;
    int nseg = n >> 4;
    const int threads = 256;
    int wblocks = (nwords + threads - 1) / threads;
    int sblocks = (nseg + threads - 1) / threads;

    k_zero<<<1, 32>>>();
    k_main<<<sblocks, threads>>>(inputs, targets, nseg);
    k_union<<<wblocks, threads>>>(nwords);
    k_area<<<sblocks, threads>>>(nseg);
    k_runs<<<sblocks, threads>>>(nseg);
    k_final<<<1, 1>>>(out, 1.0 / (double)n);
}

// round 7
// speedup vs baseline: 1.4967x; 1.4967x over previous
#include <cuda_runtime.h>
#include <math.h>

#define W_IMG 512
#define H_IMG 512
#define MAX_N (32 * W_IMG * H_IMG)
#define MAX_WORDS (MAX_N / 64)

struct __align__(8) Node { int label; int area; };
__device__ Node g_node[MAX_N];
__device__ unsigned long long g_bits[MAX_WORDS];  // fg bitmask, 64 px/word
// 0 = sum_fg bce/(w+1), 1 = sum_bg bce, 2 = sum_fg w, 3 = N_fg
__device__ double g_acc[4];

// ---------------------------------------------------------------------------
__device__ __forceinline__ int find_root(int x) {
    int p = g_node[x].label;
    while (p != x) { x = p; p = g_node[x].label; }
    return x;
}

__device__ __forceinline__ void merge(int a, int b) {
    bool done = false;
    do {
        a = find_root(a);
        b = find_root(b);
        if (a < b) { int t = a; a = b; b = t; }
        if (a != b) {
            int old = atomicMin(&g_node[a].label, b);
            done = (old == a);
            a = old;
        } else {
            done = true;
        }
    } while (!done);
}

// Run start (bit position) of the run containing set bit k of mask m.
__device__ __forceinline__ int rs_in_word(unsigned long long m, int k) {
    unsigned long long below = (k == 0) ? 0ull : ((1ull << k) - 1ull);
    unsigned long long z = (~m) & below;
    return z ? (64 - __clzll(z)) : 0;
}

// Length of the run of ones in m starting at bit k.
__device__ __forceinline__ int run_len(unsigned long long m, int k) {
    unsigned long long inv = ~(m >> k);
    return inv ? (__ffsll((long long)inv) - 1) : (64 - k);
}

__device__ __forceinline__ double warp_sum(double v) {
#pragma unroll
    for (int off = 16; off > 0; off >>= 1)
        v += __shfl_down_sync(0xFFFFFFFFu, v, off);
    return v;
}

// ---------------------------------------------------------------------------
// k_prep: thread per 4-px quad. Build word bitmask via shfl across the
// 16-lane group, init UF nodes (single 8B store) at owned run starts.
// ---------------------------------------------------------------------------
__global__ void k_prep(const float* __restrict__ tgt, int nquad) {
    int t = blockIdx.x * blockDim.x + threadIdx.x;
    if (t < nquad) {
        int w = t >> 4;          // word index (16 quads per 64-px word)
        int q = t & 15;          // quad within word
        int b0 = q << 2;         // bit offset of my quad
        float4 v = __ldg(&((const float4*)tgt)[t]);
        unsigned long long nib = 0ull;
        if (v.x > 0.f) nib |= 1ull;
        if (v.y > 0.f) nib |= 2ull;
        if (v.z > 0.f) nib |= 4ull;
        if (v.w > 0.f) nib |= 8ull;
        unsigned long long m = nib << b0;
        // OR-reduce across the aligned 16-lane group -> every lane holds word
        m |= __shfl_xor_sync(0xFFFFFFFFu, m, 1);
        m |= __shfl_xor_sync(0xFFFFFFFFu, m, 2);
        m |= __shfl_xor_sync(0xFFFFFFFFu, m, 4);
        m |= __shfl_xor_sync(0xFFFFFFFFu, m, 8);
        if (q == 0) g_bits[w] = m;

        // word-level run starts falling inside my quad (owned)
        unsigned int s = (unsigned int)(((m & ~(m << 1)) >> b0) & 0xFull);
        int base = (w << 6) + b0;
        while (s) {
            int k = __ffs(s) - 1;
            s &= s - 1;
            int node = base + k;
            *(int2*)&g_node[node] = make_int2(node, 0);
        }
    }
    if (blockIdx.x == 0 && threadIdx.x < 4) g_acc[threadIdx.x] = 0.0;
}

// ---------------------------------------------------------------------------
// k_union: word-level bitmask merges
// ---------------------------------------------------------------------------
__global__ void k_union(int nwords) {
    int w = blockIdx.x * blockDim.x + threadIdx.x;
    if (w >= nwords) return;
    unsigned long long cur = g_bits[w];
    if (!cur) return;
    int base = w << 6;
    int wx = w & 7;
    int wy = (w >> 3) & (H_IMG - 1);

    if (wx && (cur & 1ull)) {
        unsigned long long L = g_bits[w - 1];
        if (L >> 63) merge(base, ((w - 1) << 6) + rs_in_word(L, 63));
    }
    if (wy) {
        unsigned long long up = g_bits[w - 8];
        unsigned long long ov = cur & up;
        unsigned long long need = ov & ~(ov << 1);
        while (need) {
            int k = __ffsll((long long)need) - 1;
            need &= need - 1;
            merge(base + rs_in_word(cur, k),
                  ((w - 8) << 6) + rs_in_word(up, k));
        }
    }
}

// ---------------------------------------------------------------------------
// k_area: thread per quad; owned run starts -> compress to final root + area
// ---------------------------------------------------------------------------
__global__ void k_area(int nquad) {
    int t = blockIdx.x * blockDim.x + threadIdx.x;
    if (t >= nquad) return;
    int w = t >> 4;
    int q = t & 15;
    int b0 = q << 2;
    unsigned long long m = __ldg(&g_bits[w]);
    unsigned int s = (unsigned int)(((m & ~(m << 1)) >> b0) & 0xFull);
    if (!s) return;
    int base = w << 6;
    while (s) {
        int k = __ffs(s) - 1;
        s &= s - 1;
        int kk = b0 + k;
        int node = base + kk;
        int root = find_root(node);
        if (root != node) g_node[node].label = root;   // compress
        atomicAdd(&g_node[root].area, run_len(m, kk));
    }
}

// ---------------------------------------------------------------------------
// k_bce: thread per quad (grid-stride). Branchless per-pixel; fg pixels do
// independent label->area lookups (no run-carry state).
// ---------------------------------------------------------------------------
__global__ void k_bce(const float* __restrict__ in, int nquad) {
    float f0 = 0.f, f1 = 0.f, f2 = 0.f, f3 = 0.f;
    int stride = gridDim.x * blockDim.x;
    const float4* in4 = (const float4*)in;

    for (int t = blockIdx.x * blockDim.x + threadIdx.x; t < nquad; t += stride) {
        int w = t >> 4;
        int kk0 = (t & 15) << 2;
        unsigned long long m = __ldg(&g_bits[w]);
        float4 v = __ldg(&in4[t]);
        int base = w << 6;
        float xs[4] = {v.x, v.y, v.z, v.w};
#pragma unroll
        for (int l = 0; l < 4; l++) {
            int kk = kk0 + l;
            float x = xs[l];
            float gpl = __logf(1.f + __expf(-fabsf(x)));
            float b = gpl + fmaxf(x, 0.f);        // bce if bg
            if ((m >> kk) & 1ull) {
                int rs = rs_in_word(m, kk);
                int root = __ldg(&g_node[base + rs].label);   // compressed
                float a = (float)__ldg(&g_node[root].area);
                float wgt = sqrtf(a);
                f0 += __fdividef(b - x, wgt + 1.f);  // bce_fg = b - x
                f2 += wgt;
                f3 += 1.f;
            } else {
                f1 += b;
            }
        }
    }

    double d0 = f0, d1 = f1, d2 = f2, d3 = f3;
    __shared__ double sh[4][8];
    int lane = threadIdx.x & 31;
    int warp = threadIdx.x >> 5;
    d0 = warp_sum(d0); d1 = warp_sum(d1); d2 = warp_sum(d2); d3 = warp_sum(d3);
    if (lane == 0) { sh[0][warp] = d0; sh[1][warp] = d1; sh[2][warp] = d2; sh[3][warp] = d3; }
    __syncthreads();
    int nw = blockDim.x >> 5;
    if (warp == 0) {
        double v0 = (lane < nw) ? sh[0][lane] : 0.0;
        double v1 = (lane < nw) ? sh[1][lane] : 0.0;
        double v2 = (lane < nw) ? sh[2][lane] : 0.0;
        double v3 = (lane < nw) ? sh[3][lane] : 0.0;
        v0 = warp_sum(v0); v1 = warp_sum(v1); v2 = warp_sum(v2); v3 = warp_sum(v3);
        if (lane == 0) {
            atomicAdd(&g_acc[0], v0);
            atomicAdd(&g_acc[1], v1);
            atomicAdd(&g_acc[2], v2);
            atomicAdd(&g_acc[3], v3);
        }
    }
}

__global__ void k_final(float* __restrict__ out, double inv_n) {
    double nfg = g_acc[3];
    double mean_nz = g_acc[2] / (nfg > 0.0 ? nfg : 1.0);
    double loss = (g_acc[0] + g_acc[1] / (mean_nz + 1.0)) * inv_n;
    out[0] = (float)loss;
}

// ---------------------------------------------------------------------------
extern "C" void kernel_launch(void* const* d_in, const int* in_sizes, int n_in,
                              void* d_out, int out_size) {
    const float* inputs  = (const float*)d_in[0];
    const float* targets = (const float*)d_in[1];
    float* out = (float*)d_out;

    int n = in_sizes[0];
    int nwords = n >> 6;
    int nquad = n >> 2;
    const int threads = 256;
    int qblocks = (nquad + threads - 1) / threads;
    int wblocks = (nwords + threads - 1) / threads;

    k_prep<<<qblocks, threads>>>(targets, nquad);
    k_union<<<wblocks, threads>>>(nwords);
    k_area<<<qblocks, threads>>>(nquad);
    k_bce<<<2048, threads>>>(inputs, nquad);
    k_final<<<1, 1>>>(out, 1.0 / (double)n);
}